// round 1
// baseline (speedup 1.0000x reference)
#include <cuda_runtime.h>
#include <cstddef>

// SlideSum: out[b,j,f] = alpha * (x[b,i-1,f] + x[b,i,f] + x[b,i+1,f]),
// i = clamp(j, 1, L-2).  Shapes: x (64, 4096, 256) fp32, alpha scalar fp32.
// Output (64, 4096, 256) fp32.

static constexpr int B   = 64;
static constexpr int L   = 4096;
static constexpr int F   = 256;
static constexpr int F4  = F / 4;        // 64 float4 lanes per row
static constexpr int T   = 16;           // L-rows per thread tile
static constexpr int TILES_PER_B = L / T;            // 256
static constexpr int UNITS_PER_BLOCK = 4;            // 4 (b,tile) units per 256-thread block
static constexpr int GRID = B * TILES_PER_B / UNITS_PER_BLOCK;  // 4096 blocks

__device__ __forceinline__ float4 win3(const float4 a, const float4 b,
                                       const float4 c, const float alpha) {
    float4 r;
    r.x = (a.x + b.x + c.x) * alpha;
    r.y = (a.y + b.y + c.y) * alpha;
    r.z = (a.z + b.z + c.z) * alpha;
    r.w = (a.w + b.w + c.w) * alpha;
    return r;
}

__global__ __launch_bounds__(256, 8)
void SlideSum_kernel(const float* __restrict__ x,
                     const float* __restrict__ alpha_p,
                     float* __restrict__ out) {
    const float alpha = __ldg(alpha_p);

    const int f4   = threadIdx.x & (F4 - 1);          // lane within row (coalesced)
    const int sub  = threadIdx.x >> 6;                // 0..3: unit within block
    const int unit = blockIdx.x * UNITS_PER_BLOCK + sub;
    const int b    = unit / TILES_PER_B;
    const int tile = unit % TILES_PER_B;
    const int j0   = tile * T;

    const size_t col_off = (size_t)b * L * F4 + f4;
    const float4* __restrict__ cx = reinterpret_cast<const float4*>(x) + col_off;
    float4* __restrict__       co = reinterpret_cast<float4*>(out) + col_off;

    if (j0 > 0 && j0 + T < L) {
        // Interior fast path: sliding window, T+2 loads for T outputs.
        float4 a = cx[(size_t)(j0 - 1) * F4];
        float4 bb = cx[(size_t)j0 * F4];
#pragma unroll
        for (int t = 0; t < T; ++t) {
            float4 c = cx[(size_t)(j0 + t + 1) * F4];
            co[(size_t)(j0 + t) * F4] = win3(a, bb, c, alpha);
            a = bb;
            bb = c;
        }
    } else {
        // Edge tiles (first and last tile of each column): clamped indices.
#pragma unroll
        for (int t = 0; t < T; ++t) {
            const int j = j0 + t;
            int i = j;
            if (i < 1)      i = 1;
            if (i > L - 2)  i = L - 2;
            const float4 a = cx[(size_t)(i - 1) * F4];
            const float4 bb = cx[(size_t)i * F4];
            const float4 c = cx[(size_t)(i + 1) * F4];
            co[(size_t)j * F4] = win3(a, bb, c, alpha);
        }
    }
}

extern "C" void kernel_launch(void* const* d_in, const int* in_sizes, int n_in,
                              void* d_out, int out_size) {
    const float* x       = (const float*)d_in[0];
    const float* alpha_p = (const float*)d_in[1];
    float* out           = (float*)d_out;

    SlideSum_kernel<<<GRID, 256>>>(x, alpha_p, out);
}